// round 14
// baseline (speedup 1.0000x reference)
#include <cuda_runtime.h>
#include <cuda_fp16.h>
#include <cstdint>
#include <cstddef>

// Problem constants
#define T_STEPS 2048
#define BATCH   256
#define FEAT    64
#define HID     256
#define KDIM    320
#define NB      8              // batches per CTA = MMA N
#define THREADS 512
#define NC      16             // h-only k-chunks of 16 (k = 64..319)
#define ROWW    132            // words per n-row (128 data + 4 pad)
#define ROWB    (ROWW * 4)     // 528 bytes
#define BUFW    (NB * ROWW)    // 1056 words per buffer
#define BUFB    (BUFW * 4)     // 4224 bytes

// Precomputed U[t][j][b] = b0[j] + sum_{k<64} x[t,b,k]*W0[j,k]  (512MB scratch)
__device__ float g_U[(size_t)T_STEPS * HID * BATCH];

__device__ __forceinline__ void redg_add(float* p, float v) {
    asm volatile("red.global.add.f32 [%0], %1;" :: "l"(p), "f"(v) : "memory");
}
__device__ __forceinline__ void hmma_fp16(float& d0, float& d1, float& d2, float& d3,
                                          uint32_t a0, uint32_t a1, uint32_t a2, uint32_t a3,
                                          uint32_t b0, uint32_t b1) {
    asm("mma.sync.aligned.m16n8k16.row.col.f32.f16.f16.f32 "
        "{%0,%1,%2,%3}, {%4,%5,%6,%7}, {%8,%9}, {%0,%1,%2,%3};"
        : "+f"(d0), "+f"(d1), "+f"(d2), "+f"(d3)
        : "r"(a0), "r"(a1), "r"(a2), "r"(a3), "r"(b0), "r"(b1));
}
__device__ __forceinline__ uint16_t f2h(float v) {
    return __half_as_ushort(__float2half_rn(v));
}
__device__ __forceinline__ uint32_t pk(uint16_t a, uint16_t b) {
    return (uint32_t)a | ((uint32_t)b << 16);   // a = k-even in low half
}

// ---- init kernel: out[b][t] = bfc (REDG partials accumulate on top) ----
__global__ void init_out_kernel(const float* __restrict__ bfc,
                                float* __restrict__ out) {
    int i = blockIdx.x * blockDim.x + threadIdx.x;
    out[i] = bfc[0];
}

// ---- precompute U via HMMA: one CTA per t, 512 threads ----
#define XS_U2N 18     // uint2 per (nb,n) row: 16 data + 2 pad
__global__ void __launch_bounds__(512)
precompute_u_hmma(const float* __restrict__ x,    // (T, B, F)
                  const float* __restrict__ W0,   // (H, 320)
                  const float* __restrict__ b0)   // (H)
{
    __shared__ uint32_t xs32[32 * 8 * XS_U2N * 2];   // 36KB fp16 B-frags of x[t]

    const int t    = blockIdx.x;
    const int tid  = threadIdx.x;
    const int lane = tid & 31;
    const int wi   = tid >> 5;
    const int g    = lane >> 2;
    const int tq   = lane & 3;
    const int j1   = wi * 16 + g;
    const int j2   = j1 + 8;

    // A fragments: x-part chunks 0..3 (k < 64)
    uint4 afr[4];
    {
        const float* r1 = W0 + (size_t)j1 * KDIM;
        const float* r2 = W0 + (size_t)j2 * KDIM;
        #pragma unroll
        for (int c = 0; c < 4; ++c) {
            int k0 = c * 16 + tq * 2;
            afr[c] = make_uint4(
                pk(f2h(r1[k0]),     f2h(r1[k0 + 1])),
                pk(f2h(r2[k0]),     f2h(r2[k0 + 1])),
                pk(f2h(r1[k0 + 8]), f2h(r1[k0 + 9])),
                pk(f2h(r2[k0 + 8]), f2h(r2[k0 + 9])));
        }
    }
    const float b0a = b0[j1], b0b = b0[j2];

    // stage x[t] (256 b x 64 k) into fp16 B-fragments
    for (int idx = tid; idx < (BATCH * FEAT) / 4; idx += 512) {
        int b  = idx >> 4;
        int k4 = (idx & 15) * 4;
        float4 v = *reinterpret_cast<const float4*>(
            x + (size_t)t * BATCH * FEAT + b * FEAT + k4);
        int nb = b >> 3, n = b & 7, c = k4 >> 4, klx = k4 & 15;
        int xy = (klx >= 8), t0 = (klx & 7) >> 1;
        int u2 = (nb * 8 + n) * XS_U2N + c * 4 + t0;
        xs32[u2 * 2 + xy]       = pk(f2h(v.x), f2h(v.y));
        xs32[(u2 + 1) * 2 + xy] = pk(f2h(v.z), f2h(v.w));
    }
    __syncthreads();

    const uint2* xs2 = reinterpret_cast<const uint2*>(xs32);
    const int n0 = tq * 2;
    for (int nb = 0; nb < 32; ++nb) {
        float d0 = 0.f, d1 = 0.f, d2 = 0.f, d3 = 0.f;
        #pragma unroll
        for (int c = 0; c < 4; ++c) {
            uint2 Bv = xs2[(nb * 8 + g) * XS_U2N + c * 4 + tq];
            hmma_fp16(d0, d1, d2, d3,
                      afr[c].x, afr[c].y, afr[c].z, afr[c].w, Bv.x, Bv.y);
        }
        *reinterpret_cast<float2*>(
            g_U + ((size_t)t * HID + j1) * BATCH + nb * 8 + n0) =
            make_float2(d0 + b0a, d1 + b0a);
        *reinterpret_cast<float2*>(
            g_U + ((size_t)t * HID + j2) * BATCH + nb * 8 + n0) =
            make_float2(d2 + b0b, d3 + b0b);
    }
}

// ---- serial RNN loop: K = 256 (h only), U added via accumulator preload ----
__global__ void __launch_bounds__(THREADS, 1)
rnn_hmma_kernel(const float* __restrict__ W0,   // (H, 320) — h cols 64..319
                const float* __restrict__ Wfc,  // (1, H)
                float* __restrict__ out)        // (B, T)
{
    __shared__ uint32_t buf[2][BUFW];

    const int tid  = threadIdx.x;
    const int lane = tid & 31;
    const int wi   = tid >> 5;            // warp 0..15 — owns j in [wi*16, wi*16+16)
    const int g    = lane >> 2;
    const int tq   = lane & 3;
    const int bg   = blockIdx.x * NB;

    const int j1 = wi * 16 + g;
    const int j2 = j1 + 8;

    // ---- A fragments: h-part of W0 in RF as fp16 (chunks k = 64 + c*16) ----
    uint4 afr[NC];
    {
        const float* r1 = W0 + (size_t)j1 * KDIM + FEAT;
        const float* r2 = W0 + (size_t)j2 * KDIM + FEAT;
        #pragma unroll
        for (int c = 0; c < NC; ++c) {
            int k0 = c * 16 + tq * 2;
            afr[c] = make_uint4(
                pk(f2h(r1[k0]),     f2h(r1[k0 + 1])),
                pk(f2h(r2[k0]),     f2h(r2[k0 + 1])),
                pk(f2h(r1[k0 + 8]), f2h(r1[k0 + 9])),
                pk(f2h(r2[k0 + 8]), f2h(r2[k0 + 9])));
        }
    }
    const float wf1 = Wfc[j1], wf2 = Wfc[j2];
    const int n0 = tq * 2;

    // h store geometry: k' = j (0..255): chunk = wi, subline = g>>1, xy via g&8
    const int hbyte0 = n0 * ROWB + wi * 32 + (g >> 1) * 8 + (g & 1) * 2;  // j1 (xy=0)
    const int hbyte1 = hbyte0 + ROWB;                                      // n0+1

    // zero both buffers (h(0) = 0)
    for (int i = tid; i < 2 * BUFW; i += THREADS) (&buf[0][0])[i] = 0u;
    __syncthreads();

    // ---- U prefetch: regs hold U[t] and U[t+1] ----
    const size_t ustep = (size_t)HID * BATCH;
    const float* U1 = g_U + (size_t)j1 * BATCH + bg + n0;
    const float* U2 = g_U + (size_t)j2 * BATCH + bg + n0;
    float2 ua   = *reinterpret_cast<const float2*>(U1);
    float2 ub   = *reinterpret_cast<const float2*>(U2);
    float2 ua_n = *reinterpret_cast<const float2*>(U1 + ustep);
    float2 ub_n = *reinterpret_cast<const float2*>(U2 + ustep);
    U1 += 2 * ustep;
    U2 += 2 * ustep;

    char* const bufc = reinterpret_cast<char*>(buf);
    const int bbase = g * (ROWW / 2) + tq;    // uint2 units: 66 per n-row

    for (int t = 0; t < T_STEPS; ++t) {
        const int p = t & 1;
        const int q = p ^ 1;

        // ---- 16 HMMAs, 4 rotating chains; chain 0 preloaded with U ----
        float dacc[16];
        dacc[0] = ua.x; dacc[1] = ua.y; dacc[2] = ub.x; dacc[3] = ub.y;
        #pragma unroll
        for (int i = 4; i < 16; ++i) dacc[i] = 0.f;

        const uint2* Bb = reinterpret_cast<const uint2*>(buf[p]) + bbase;
        #pragma unroll
        for (int c = 0; c < NC; ++c) {
            uint2 Bv = Bb[c * 4];
            const int ch = (c & 3) * 4;
            hmma_fp16(dacc[ch], dacc[ch+1], dacc[ch+2], dacc[ch+3],
                      afr[c].x, afr[c].y, afr[c].z, afr[c].w, Bv.x, Bv.y);
        }
        float d0 = (dacc[0] + dacc[4]) + (dacc[8]  + dacc[12]);  // (j1, n0)
        float d1 = (dacc[1] + dacc[5]) + (dacc[9]  + dacc[13]);  // (j1, n0+1)
        float d2 = (dacc[2] + dacc[6]) + (dacc[10] + dacc[14]);  // (j2, n0)
        float d3 = (dacc[3] + dacc[7]) + (dacc[11] + dacc[15]);  // (j2, n0+1)

        // ---- tanh (accurate exp identity) ----
        float e00 = __expf(2.f * d0);
        float e01 = __expf(2.f * d1);
        float e10 = __expf(2.f * d2);
        float e11 = __expf(2.f * d3);
        float h00 = 1.f - __fdividef(2.f, e00 + 1.f);
        float h01 = 1.f - __fdividef(2.f, e01 + 1.f);
        float h10 = 1.f - __fdividef(2.f, e10 + 1.f);
        float h11 = 1.f - __fdividef(2.f, e11 + 1.f);

        // ---- write h (fp16) into next buffer ----
        {
            char* bq = bufc + q * BUFB;
            *reinterpret_cast<uint16_t*>(bq + hbyte0)     = f2h(h00);
            *reinterpret_cast<uint16_t*>(bq + hbyte0 + 4) = f2h(h10);
            *reinterpret_cast<uint16_t*>(bq + hbyte1)     = f2h(h01);
            *reinterpret_cast<uint16_t*>(bq + hbyte1 + 4) = f2h(h11);
        }

        // split barrier: release h stores; tail runs in barrier shadow
        asm volatile("bar.arrive 0, 1024;" ::: "memory");

        // ---- shadow: U prefetch rotation + output partials ----
        ua = ua_n; ub = ub_n;
        if (t + 2 < T_STEPS) {
            ua_n = *reinterpret_cast<const float2*>(U1);
            ub_n = *reinterpret_cast<const float2*>(U2);
            U1 += ustep; U2 += ustep;
        }

        float po0 = h00 * wf1 + h10 * wf2;
        float po1 = h01 * wf1 + h11 * wf2;
        po0 += __shfl_xor_sync(0xffffffffu, po0, 4);
        po1 += __shfl_xor_sync(0xffffffffu, po1, 4);
        po0 += __shfl_xor_sync(0xffffffffu, po0, 8);
        po1 += __shfl_xor_sync(0xffffffffu, po1, 8);
        po0 += __shfl_xor_sync(0xffffffffu, po0, 16);
        po1 += __shfl_xor_sync(0xffffffffu, po1, 16);
        if (g == 0) {
            redg_add(out + (size_t)(bg + n0) * T_STEPS + t,     po0);
            redg_add(out + (size_t)(bg + n0 + 1) * T_STEPS + t, po1);
        }

        asm volatile("bar.sync 0, 1024;" ::: "memory");
    }
}

extern "C" void kernel_launch(void* const* d_in, const int* in_sizes, int n_in,
                              void* d_out, int out_size) {
    const float* x   = (const float*)d_in[0];
    const float* W0  = (const float*)d_in[1];
    const float* b0  = (const float*)d_in[2];
    const float* Wfc = (const float*)d_in[3];
    const float* bfc = (const float*)d_in[4];
    float* out = (float*)d_out;
    (void)in_sizes; (void)n_in; (void)out_size;

    // 1) out[b][t] = bfc
    init_out_kernel<<<(BATCH * T_STEPS) / 256, 256>>>(bfc, out);

    // 2) precompute U = b0 + x*W0x^T via HMMA (all SMs, store-BW bound)
    precompute_u_hmma<<<T_STEPS, 512>>>(x, W0, b0);

    // 3) serial RNN loop on K=256 only: 32 CTAs, 512 thr, h-weights in RF
    rnn_hmma_kernel<<<BATCH / NB, THREADS>>>(W0, Wfc, out);
}

// round 15
// speedup vs baseline: 1.3210x; 1.3210x over previous
#include <cuda_runtime.h>
#include <cuda_fp16.h>
#include <cstdint>
#include <cstddef>

// Problem constants
#define T_STEPS 2048
#define BATCH   256
#define FEAT    64
#define KDIM    320            // FEAT + HID
#define NB      8              // batches per CTA = MMA N
#define THREADS 512
#define NPAIRS  10             // chunk-pairs (20 k-chunks of 16)
#define ROWB    704            // bytes per n-row (640 data + 64 pad; 704/16=44 ≡ 4 mod 8)
#define BUFB    (NB * ROWB)    // 5632 bytes per buffer
#define BUFW    (BUFB / 4)     // 1408 words

__device__ __forceinline__ void redg_add(float* p, float v) {
    asm volatile("red.global.add.f32 [%0], %1;" :: "l"(p), "f"(v) : "memory");
}
__device__ __forceinline__ void hmma_fp16(float& d0, float& d1, float& d2, float& d3,
                                          uint32_t a0, uint32_t a1, uint32_t a2, uint32_t a3,
                                          uint32_t b0, uint32_t b1) {
    asm("mma.sync.aligned.m16n8k16.row.col.f32.f16.f16.f32 "
        "{%0,%1,%2,%3}, {%4,%5,%6,%7}, {%8,%9}, {%0,%1,%2,%3};"
        : "+f"(d0), "+f"(d1), "+f"(d2), "+f"(d3)
        : "r"(a0), "r"(a1), "r"(a2), "r"(a3), "r"(b0), "r"(b1));
}
__device__ __forceinline__ uint16_t f2h(float v) {
    return __half_as_ushort(__float2half_rn(v));
}
__device__ __forceinline__ uint32_t pk(uint16_t a, uint16_t b) {
    return (uint32_t)a | ((uint32_t)b << 16);   // a = k-even in low half
}
__device__ __forceinline__ float rcpa(float v) {
    float r;
    asm("rcp.approx.f32 %0, %1;" : "=f"(r) : "f"(v));
    return r;
}

// byte offset within a buffer for (n, chunk c, subline t, xy, parity)
// chunk-pair layout: pair P at P*64; odd chunk at +8; subline t at t*16; xy at *4
__device__ __forceinline__ int bofs(int n, int c, int t, int xy, int par) {
    return n * ROWB + (c >> 1) * 64 + (c & 1) * 8 + t * 16 + xy * 4 + par * 2;
}

// ---- init kernel: out[b][t] = bfc (REDG partials accumulate on top) ----
__global__ void init_out_kernel(const float* __restrict__ bfc,
                                float* __restrict__ out) {
    int i = blockIdx.x * blockDim.x + threadIdx.x;
    out[i] = bfc[0];
}

__global__ void __launch_bounds__(THREADS, 1)
rnn_hmma_kernel(const float* __restrict__ x,    // (T, B, F)
                const float* __restrict__ W0,   // (H, 320)
                const float* __restrict__ b0,   // (H)
                const float* __restrict__ Wfc,  // (1, H)
                float* __restrict__ out)        // (B, T)
{
    __shared__ __align__(16) uint32_t buf[2][BUFW];

    const int tid  = threadIdx.x;
    const int lane = tid & 31;
    const int wi   = tid >> 5;            // warp 0..15 — owns j in [wi*16, wi*16+16)
    const int g    = lane >> 2;           // fragment group 0..7
    const int tq   = lane & 3;            // thread-in-group 0..3
    const int bg   = blockIdx.x * NB;     // first batch of this CTA

    const int j1 = wi * 16 + g;           // A rows this thread owns
    const int j2 = j1 + 8;

    // ---- A fragments (full W0 in RF as fp16): 20 chunks x 4 regs ----
    uint4 afr[2 * NPAIRS];
    {
        const float* r1 = W0 + (size_t)j1 * KDIM;
        const float* r2 = W0 + (size_t)j2 * KDIM;
        #pragma unroll
        for (int c = 0; c < 2 * NPAIRS; ++c) {
            int k0 = c * 16 + tq * 2;
            afr[c] = make_uint4(
                pk(f2h(r1[k0]),     f2h(r1[k0 + 1])),
                pk(f2h(r2[k0]),     f2h(r2[k0 + 1])),
                pk(f2h(r1[k0 + 8]), f2h(r1[k0 + 9])),
                pk(f2h(r2[k0 + 8]), f2h(r2[k0 + 9])));
        }
    }

    const float b0a = b0[j1], b0b = b0[j2];
    const float wf1 = Wfc[j1], wf2 = Wfc[j2];
    const int n0 = tq * 2;

    // ---- h store geometry: k = 64 + j1 -> chunk 4+wi, t = g>>1, xy=0 (j2: xy=1) ----
    const int hbyte0 = bofs(n0, 4 + wi, g >> 1, 0, g & 1);
    const int hbyte1 = hbyte0 + ROWB;      // n0+1

    // ---- x deposit geometry: threads 0..127 own (n_x, k4..k4+3) ----
    const bool xown = tid < 128;
    const int n_x = tid >> 4;              // 0..7
    const int k4  = (tid & 15) * 4;        // 0..60
    const int c_x = k4 >> 4;
    const int klx = k4 & 15;
    const int xyx = (klx >= 8) ? 1 : 0;
    const int t0x = (klx & 7) >> 1;        // 0 or 2
    const int xbyte = bofs(n_x, c_x, t0x, xyx, 0);   // second kpair at +16

    // zero both buffers (h region of buf0 must be 0 at t=0)
    for (int i = tid; i < 2 * BUFW; i += THREADS) (&buf[0][0])[i] = 0u;
    __syncthreads();

    char* const bufc = reinterpret_cast<char*>(buf);
    float4 xv = make_float4(0.f, 0.f, 0.f, 0.f);
    if (xown) {
        float4 v = *reinterpret_cast<const float4*>(
            x + ((size_t)0 * BATCH + bg + n_x) * FEAT + k4);
        *reinterpret_cast<uint32_t*>(bufc + xbyte)      = pk(f2h(v.x), f2h(v.y));
        *reinterpret_cast<uint32_t*>(bufc + xbyte + 16) = pk(f2h(v.z), f2h(v.w));
        xv = *reinterpret_cast<const float4*>(
            x + ((size_t)1 * BATCH + bg + n_x) * FEAT + k4);
    }
    __syncthreads();

    // B-frag base (uint4 index): (n = g, pair P, subline tq) -> g*44 + tq
    const int bbase = g * (ROWB / 16) + tq;

    for (int t = 0; t < T_STEPS; ++t) {
        const int p = t & 1;
        const int q = p ^ 1;

        // ---- 20 HMMAs via 10 LDS.128, 4 rotating accumulator chains ----
        float dacc[16];
        #pragma unroll
        for (int i = 0; i < 16; ++i) dacc[i] = 0.f;

        const uint4* Bb = reinterpret_cast<const uint4*>(buf[p]) + bbase;
        #pragma unroll
        for (int P = 0; P < NPAIRS; ++P) {
            uint4 Bv = Bb[P * 4];              // chunks 2P (x,y) and 2P+1 (z,w)
            const int ch0 = ((2 * P) & 3) * 4;
            const int ch1 = ((2 * P + 1) & 3) * 4;
            hmma_fp16(dacc[ch0], dacc[ch0+1], dacc[ch0+2], dacc[ch0+3],
                      afr[2*P].x, afr[2*P].y, afr[2*P].z, afr[2*P].w, Bv.x, Bv.y);
            hmma_fp16(dacc[ch1], dacc[ch1+1], dacc[ch1+2], dacc[ch1+3],
                      afr[2*P+1].x, afr[2*P+1].y, afr[2*P+1].z, afr[2*P+1].w, Bv.z, Bv.w);
        }
        float d0 = (dacc[0] + dacc[4]) + (dacc[8]  + dacc[12]);  // (j1, n0)
        float d1 = (dacc[1] + dacc[5]) + (dacc[9]  + dacc[13]);  // (j1, n0+1)
        float d2 = (dacc[2] + dacc[6]) + (dacc[10] + dacc[14]);  // (j2, n0)
        float d3 = (dacc[3] + dacc[7]) + (dacc[11] + dacc[15]);  // (j2, n0+1)

        // ---- tanh: 4x EX2 + ONE shared RCP (product trick), clamp +-10 ----
        d0 = fminf(fmaxf(d0 + b0a, -10.f), 10.f);
        d1 = fminf(fmaxf(d1 + b0a, -10.f), 10.f);
        d2 = fminf(fmaxf(d2 + b0b, -10.f), 10.f);
        d3 = fminf(fmaxf(d3 + b0b, -10.f), 10.f);
        float q00 = __expf(2.f * d0) + 1.f;
        float q01 = __expf(2.f * d1) + 1.f;
        float q10 = __expf(2.f * d2) + 1.f;
        float q11 = __expf(2.f * d3) + 1.f;
        float p01 = q00 * q01, p23 = q10 * q11;
        float r   = rcpa(p01 * p23);
        float r01 = r * p23, r23 = r * p01;      // 1/p01, 1/p23
        float h00 = fmaf(r01 * q01, -2.f, 1.f);  // 1 - 2/q00
        float h01 = fmaf(r01 * q00, -2.f, 1.f);
        float h10 = fmaf(r23 * q11, -2.f, 1.f);
        float h11 = fmaf(r23 * q10, -2.f, 1.f);

        // ---- write h (fp16) into next buffer ----
        {
            char* bq = bufc + q * BUFB;
            *reinterpret_cast<uint16_t*>(bq + hbyte0)     = f2h(h00);  // (j1, n0)
            *reinterpret_cast<uint16_t*>(bq + hbyte0 + 4) = f2h(h10);  // (j2, n0)
            *reinterpret_cast<uint16_t*>(bq + hbyte1)     = f2h(h01);  // (j1, n0+1)
            *reinterpret_cast<uint16_t*>(bq + hbyte1 + 4) = f2h(h11);  // (j2, n0+1)
        }

        // ---- deposit x_{t+1} into next buffer (stores must precede arrive) ----
        if (xown) {
            char* bq = bufc + q * BUFB;
            *reinterpret_cast<uint32_t*>(bq + xbyte)      = pk(f2h(xv.x), f2h(xv.y));
            *reinterpret_cast<uint32_t*>(bq + xbyte + 16) = pk(f2h(xv.z), f2h(xv.w));
        }

        // split barrier: release stores; tail runs in the barrier shadow
        asm volatile("bar.arrive 0, 1024;" ::: "memory");

        // ---- shadow: x prefetch + output partials ----
        if (xown && (t + 2) < T_STEPS)
            xv = *reinterpret_cast<const float4*>(
                x + ((size_t)(t + 2) * BATCH + bg + n_x) * FEAT + k4);

        float po0 = h00 * wf1 + h10 * wf2;
        float po1 = h01 * wf1 + h11 * wf2;
        po0 += __shfl_xor_sync(0xffffffffu, po0, 4);
        po1 += __shfl_xor_sync(0xffffffffu, po1, 4);
        po0 += __shfl_xor_sync(0xffffffffu, po0, 8);
        po1 += __shfl_xor_sync(0xffffffffu, po1, 8);
        po0 += __shfl_xor_sync(0xffffffffu, po0, 16);
        po1 += __shfl_xor_sync(0xffffffffu, po1, 16);
        if (g == 0) {
            redg_add(out + (size_t)(bg + n0) * T_STEPS + t,     po0);
            redg_add(out + (size_t)(bg + n0 + 1) * T_STEPS + t, po1);
        }

        asm volatile("bar.sync 0, 1024;" ::: "memory");
    }
}

extern "C" void kernel_launch(void* const* d_in, const int* in_sizes, int n_in,
                              void* d_out, int out_size) {
    const float* x   = (const float*)d_in[0];
    const float* W0  = (const float*)d_in[1];
    const float* b0  = (const float*)d_in[2];
    const float* Wfc = (const float*)d_in[3];
    const float* bfc = (const float*)d_in[4];
    float* out = (float*)d_out;
    (void)in_sizes; (void)n_in; (void)out_size;

    // 1) out[b][t] = bfc
    init_out_kernel<<<(BATCH * T_STEPS) / 256, 256>>>(bfc, out);

    // 2) single-CTA-per-8-batches HMMA RNN: 32 CTAs, 512 thr, full W0 in RF (fp16)
    rnn_hmma_kernel<<<BATCH / NB, THREADS>>>(x, W0, b0, Wfc, out);
}